// round 3
// baseline (speedup 1.0000x reference)
#include <cuda_runtime.h>
#include <math.h>

#define BB   16384
#define DIM  1024
#define HID  64
#define TWOD 2048

// ---------------- device scratch (no allocations allowed) ----------------
__device__ float g_z1[BB*HID];
__device__ float g_s1[BB*HID];
__device__ float g_h1[BB*HID];
__device__ float g_s2[BB*HID];
__device__ float g_h3[BB*HID];
__device__ float g_phalf[(size_t)BB*DIM];
__device__ float g_W2T[DIM*HID];
__device__ float g_w2s[HID];
__device__ float g_Gqp[HID*HID];
__device__ float g_invm[DIM];

// ---------------- helpers ----------------
__device__ __forceinline__ float dt_of(const float* dtp){
    float x = __ldg(dtp);
    return 1.0f/(1.0f + expf(-x));
}
__device__ __forceinline__ float gelu_f(float x){
    return x * 0.5f * (1.0f + erff(x * 0.70710678118654752440f));
}
__device__ __forceinline__ float dgelu_f(float x){
    float cdf = 0.5f * (1.0f + erff(x * 0.70710678118654752440f));
    float pdf = 0.39894228040143267794f * expf(-0.5f * x * x);
    return cdf + x * pdf;
}

#define FMA16(acc, xv, wv) do {                          \
    acc[0][0] = fmaf(xv.x, wv.x, acc[0][0]);             \
    acc[0][1] = fmaf(xv.x, wv.y, acc[0][1]);             \
    acc[0][2] = fmaf(xv.x, wv.z, acc[0][2]);             \
    acc[0][3] = fmaf(xv.x, wv.w, acc[0][3]);             \
    acc[1][0] = fmaf(xv.y, wv.x, acc[1][0]);             \
    acc[1][1] = fmaf(xv.y, wv.y, acc[1][1]);             \
    acc[1][2] = fmaf(xv.y, wv.z, acc[1][2]);             \
    acc[1][3] = fmaf(xv.y, wv.w, acc[1][3]);             \
    acc[2][0] = fmaf(xv.z, wv.x, acc[2][0]);             \
    acc[2][1] = fmaf(xv.z, wv.y, acc[2][1]);             \
    acc[2][2] = fmaf(xv.z, wv.z, acc[2][2]);             \
    acc[2][3] = fmaf(xv.z, wv.w, acc[2][3]);             \
    acc[3][0] = fmaf(xv.w, wv.x, acc[3][0]);             \
    acc[3][1] = fmaf(xv.w, wv.y, acc[3][1]);             \
    acc[3][2] = fmaf(xv.w, wv.z, acc[3][2]);             \
    acc[3][3] = fmaf(xv.w, wv.w, acc[3][3]);             \
} while(0)

// 4x4 register tile MMA over KK contraction steps.
// SA: [k][m] (row index m, pad 68), SB: [k][n] (pad 68).
template<int KK>
__device__ __forceinline__ void mmaT(float acc[4][4], const float* SA, const float* SB,
                                     int mi4, int ni4){
    #pragma unroll
    for (int k = 0; k < KK; ++k){
        float4 xv = *(const float4*)(SA + k*68 + mi4);
        float4 wv = *(const float4*)(SB + k*68 + ni4);
        FMA16(acc, xv, wv);
    }
}

// Load a 64x64 row-major tile (row stride 64) TRANSPOSED into S[col][row], pad 68.
__device__ __forceinline__ void loadT64(float* S, const float* __restrict__ src, int t){
    #pragma unroll
    for (int i2 = 0; i2 < 4; ++i2){
        int e = t + i2*256;              // float4 index 0..1023
        int row = e >> 4, c4 = e & 15;
        float4 v = *(const float4*)(src + row*64 + c4*4);
        S[(c4*4+0)*68 + row] = v.x;
        S[(c4*4+1)*68 + row] = v.y;
        S[(c4*4+2)*68 + row] = v.z;
        S[(c4*4+3)*68 + row] = v.w;
    }
}
// Natural copy of 64x64 row-major tile into S[row][col] with pad 68.
__device__ __forceinline__ void loadN64(float* S, const float* __restrict__ src, int t){
    #pragma unroll
    for (int i2 = 0; i2 < 4; ++i2){
        int e = t + i2*256;
        int row = e >> 4, c4 = e & 15;
        float4 v = *(const float4*)(src + row*64 + c4*4);
        *(float4*)(S + row*68 + c4*4) = v;
    }
}

// ---------------- prep: w2s, invm, W2T, Gqp = W1q^T W1p ----------------
__global__ __launch_bounds__(256) void prep_kernel(const float* __restrict__ W1,
                                                   const float* __restrict__ W2,
                                                   const float* __restrict__ mass){
    int b = blockIdx.x, t = threadIdx.x;
    if (b == 0){
        if (t < HID){
            float s = 0.f;
            for (int d = 0; d < DIM; ++d) s += W2[t*DIM + d];
            g_w2s[t] = s;
        }
        for (int i = t; i < DIM; i += 256) g_invm[i] = 1.0f / mass[i];
    } else if (b <= 16){
        int base = (b-1)*4096;
        for (int i = t; i < 4096; i += 256){
            int idx = base + i;
            int j = idx >> 10, d = idx & 1023;
            g_W2T[d*HID + j] = W2[idx];
        }
    } else {
        // blocks 17..20: Gqp rows i0..i0+15
        __shared__ float Xc[64][17];
        __shared__ float Yc[64][68];
        int i0 = (b-17)*16;
        int i_ = t & 15, j4 = (t >> 4) * 4;
        float acc[4] = {0.f,0.f,0.f,0.f};
        for (int kc = 0; kc < DIM; kc += 64){
            for (int e = t; e < 1024; e += 256){
                int k = e >> 4, i = e & 15;
                Xc[k][i] = W1[(kc+k)*HID + i0 + i];
            }
            for (int e = t; e < 1024; e += 256){
                int k = e >> 4, c4 = e & 15;
                float4 v = *(const float4*)(W1 + (size_t)(DIM + kc + k)*HID + c4*4);
                *(float4*)&Yc[k][c4*4] = v;
            }
            __syncthreads();
            #pragma unroll 8
            for (int k = 0; k < 64; ++k){
                float x = Xc[k][i_];
                float4 y = *(const float4*)&Yc[k][j4];
                acc[0] = fmaf(x, y.x, acc[0]);
                acc[1] = fmaf(x, y.y, acc[1]);
                acc[2] = fmaf(x, y.z, acc[2]);
                acc[3] = fmaf(x, y.w, acc[3]);
            }
            __syncthreads();
        }
        #pragma unroll
        for (int jj = 0; jj < 4; ++jj) g_Gqp[(i0+i_)*HID + j4+jj] = acc[jj];
    }
}

// ---------------- kA: z1 = [q p] @ W1 + b1 ; h1, s1 ----------------
__global__ __launch_bounds__(256) void kA(const float* __restrict__ q,
                                          const float* __restrict__ p,
                                          const float* __restrict__ W1,
                                          const float* __restrict__ b1){
    __shared__ float SA[32*68];
    __shared__ float SB[32*68];
    int t = threadIdx.x;
    int r0 = blockIdx.x * 64;
    int mi4 = (t & 15) * 4, ni4 = (t >> 4) * 4;
    float acc[4][4] = {};
    for (int kk = 0; kk < TWOD; kk += 32){
        const float* src = (kk < DIM) ? (q + kk) : (p + (kk - DIM));
        #pragma unroll
        for (int i2 = 0; i2 < 2; ++i2){
            int e = t + i2*256;
            int row = e >> 3, kq = e & 7;
            float4 v = *(const float4*)(src + (size_t)(r0+row)*DIM + kq*4);
            SA[(kq*4+0)*68 + row] = v.x;
            SA[(kq*4+1)*68 + row] = v.y;
            SA[(kq*4+2)*68 + row] = v.z;
            SA[(kq*4+3)*68 + row] = v.w;
        }
        #pragma unroll
        for (int i2 = 0; i2 < 2; ++i2){
            int e = t + i2*256;
            int kr = e >> 4, c4 = e & 15;
            float4 v = *(const float4*)(W1 + (size_t)(kk+kr)*HID + c4*4);
            *(float4*)(SB + kr*68 + c4*4) = v;
        }
        __syncthreads();
        mmaT<32>(acc, SA, SB, mi4, ni4);
        __syncthreads();
    }
    float4 bv  = *(const float4*)(b1 + ni4);
    float4 wsv = *(const float4*)(g_w2s + ni4);
    #pragma unroll
    for (int ii = 0; ii < 4; ++ii){
        int r = r0 + mi4 + ii;
        float z0 = acc[ii][0] + bv.x;
        float z1 = acc[ii][1] + bv.y;
        float z2 = acc[ii][2] + bv.z;
        float z3 = acc[ii][3] + bv.w;
        float4 zf = {z0, z1, z2, z3};
        float4 hf = {gelu_f(z0), gelu_f(z1), gelu_f(z2), gelu_f(z3)};
        float4 sf = {dgelu_f(z0)*wsv.x, dgelu_f(z1)*wsv.y,
                     dgelu_f(z2)*wsv.z, dgelu_f(z3)*wsv.w};
        *(float4*)(g_z1 + r*HID + ni4) = zf;
        *(float4*)(g_h1 + r*HID + ni4) = hf;
        *(float4*)(g_s1 + r*HID + ni4) = sf;
    }
}

// ---------------- kB: dHq1 -> p_half, q_new ; H1 -> out_e (temp) ----------------
__global__ __launch_bounds__(256) void kB(const float* __restrict__ q,
                                          const float* __restrict__ p,
                                          const float* __restrict__ W1,
                                          const float* __restrict__ b2,
                                          const float* __restrict__ dtp,
                                          float* __restrict__ out_q,
                                          float* __restrict__ out_e){
    __shared__ float SA[64*68];
    __shared__ float SB[64*68];
    int t = threadIdx.x;
    int r0 = blockIdx.x * 64, d0 = blockIdx.y * 64;
    int mi4 = (t & 15) * 4, ni4 = (t >> 4) * 4;
    float dt = dt_of(dtp), hdt = 0.5f*dt;

    // phase 1: dHq1[r][d] = sum_j s1[r][j] * W1q[d][j]
    loadT64(SA, g_s1 + r0*HID, t);
    loadT64(SB, W1 + (size_t)d0*HID, t);
    __syncthreads();
    float acc[4][4] = {};
    mmaT<64>(acc, SA, SB, mi4, ni4);
    float4 iv = *(const float4*)(g_invm + d0 + ni4);
    #pragma unroll
    for (int ii = 0; ii < 4; ++ii){
        int r = r0 + mi4 + ii;
        size_t off = (size_t)r*DIM + d0 + ni4;
        float4 pv = *(const float4*)(p + off);
        float4 qv = *(const float4*)(q + off);
        float4 ph, qn;
        ph.x = pv.x - hdt*acc[ii][0];  qn.x = qv.x + dt*iv.x*ph.x;
        ph.y = pv.y - hdt*acc[ii][1];  qn.y = qv.y + dt*iv.y*ph.y;
        ph.z = pv.z - hdt*acc[ii][2];  qn.z = qv.z + dt*iv.z*ph.z;
        ph.w = pv.w - hdt*acc[ii][3];  qn.w = qv.w + dt*iv.w*ph.w;
        *(float4*)(g_phalf + off) = ph;
        *(float4*)(out_q   + off) = qn;
    }
    __syncthreads();

    // phase 2: H1[r][d] = sum_j h1[r][j] * W2T[d][j] + b2[d]
    loadT64(SA, g_h1 + r0*HID, t);
    loadT64(SB, g_W2T + (size_t)d0*HID, t);
    __syncthreads();
    float accH[4][4] = {};
    mmaT<64>(accH, SA, SB, mi4, ni4);
    float4 bv = *(const float4*)(b2 + d0 + ni4);
    #pragma unroll
    for (int ii = 0; ii < 4; ++ii){
        int r = r0 + mi4 + ii;
        size_t off = (size_t)r*DIM + d0 + ni4;
        float4 hv;
        hv.x = accH[ii][0] + bv.x;
        hv.y = accH[ii][1] + bv.y;
        hv.z = accH[ii][2] + bv.z;
        hv.w = accH[ii][3] + bv.w;
        *(float4*)(out_e + off) = hv;
    }
}

// ---------------- kU: u = (phalf/m)@W1q ; z2, s2 ; z3, h3 ----------------
__global__ __launch_bounds__(256) void kU(const float* __restrict__ W1,
                                          const float* __restrict__ dtp){
    __shared__ float SA[64*68];
    __shared__ float SB[64*68];
    int t = threadIdx.x;
    int r0 = blockIdx.x * 64;
    int mi4 = (t & 15) * 4, ni4 = (t >> 4) * 4;
    float dt = dt_of(dtp), hdt = 0.5f*dt;

    float acc[4][4] = {};
    for (int kk = 0; kk < DIM; kk += 32){
        #pragma unroll
        for (int i2 = 0; i2 < 2; ++i2){
            int e = t + i2*256;
            int row = e >> 3, kq = e & 7;
            float4 v  = *(const float4*)(g_phalf + (size_t)(r0+row)*DIM + kk + kq*4);
            float4 im = *(const float4*)(g_invm + kk + kq*4);
            SA[(kq*4+0)*68 + row] = v.x*im.x;
            SA[(kq*4+1)*68 + row] = v.y*im.y;
            SA[(kq*4+2)*68 + row] = v.z*im.z;
            SA[(kq*4+3)*68 + row] = v.w*im.w;
        }
        #pragma unroll
        for (int i2 = 0; i2 < 2; ++i2){
            int e = t + i2*256;
            int kr = e >> 4, c4 = e & 15;
            float4 v = *(const float4*)(W1 + (size_t)(kk+kr)*HID + c4*4);
            *(float4*)(SB + kr*68 + c4*4) = v;
        }
        __syncthreads();
        mmaT<32>(acc, SA, SB, mi4, ni4);
        __syncthreads();
    }

    // corr1 = s1 @ Gqp
    loadT64(SA, g_s1 + r0*HID, t);
    loadN64(SB, g_Gqp, t);
    __syncthreads();
    float corr[4][4] = {};
    mmaT<64>(corr, SA, SB, mi4, ni4);

    float z2v[4][4], s2v[4][4];
    float4 wsv = *(const float4*)(g_w2s + ni4);
    #pragma unroll
    for (int ii = 0; ii < 4; ++ii){
        int r = r0 + mi4 + ii;
        float4 z1v = *(const float4*)(g_z1 + r*HID + ni4);
        z2v[ii][0] = z1v.x + dt*acc[ii][0] - hdt*corr[ii][0];
        z2v[ii][1] = z1v.y + dt*acc[ii][1] - hdt*corr[ii][1];
        z2v[ii][2] = z1v.z + dt*acc[ii][2] - hdt*corr[ii][2];
        z2v[ii][3] = z1v.w + dt*acc[ii][3] - hdt*corr[ii][3];
        s2v[ii][0] = dgelu_f(z2v[ii][0]) * wsv.x;
        s2v[ii][1] = dgelu_f(z2v[ii][1]) * wsv.y;
        s2v[ii][2] = dgelu_f(z2v[ii][2]) * wsv.z;
        s2v[ii][3] = dgelu_f(z2v[ii][3]) * wsv.w;
        float4 sf = {s2v[ii][0], s2v[ii][1], s2v[ii][2], s2v[ii][3]};
        *(float4*)(g_s2 + r*HID + ni4) = sf;
    }
    __syncthreads();
    // scatter s2 transposed into SA: SA[j][row]
    #pragma unroll
    for (int ii = 0; ii < 4; ++ii)
        #pragma unroll
        for (int jj = 0; jj < 4; ++jj)
            SA[(ni4+jj)*68 + (mi4+ii)] = s2v[ii][jj];
    __syncthreads();
    float c3[4][4] = {};
    mmaT<64>(c3, SA, SB, mi4, ni4);
    #pragma unroll
    for (int ii = 0; ii < 4; ++ii){
        int r = r0 + mi4 + ii;
        float z30 = z2v[ii][0] - hdt*c3[ii][0];
        float z31 = z2v[ii][1] - hdt*c3[ii][1];
        float z32 = z2v[ii][2] - hdt*c3[ii][2];
        float z33 = z2v[ii][3] - hdt*c3[ii][3];
        float4 hf = {gelu_f(z30), gelu_f(z31), gelu_f(z32), gelu_f(z33)};
        *(float4*)(g_h3 + r*HID + ni4) = hf;
    }
}

// ---------------- kD: dHq2 -> p_new ; H3 -> energy = |H1 - H3| ----------------
__global__ __launch_bounds__(256) void kD(const float* __restrict__ W1,
                                          const float* __restrict__ b2,
                                          const float* __restrict__ dtp,
                                          float* __restrict__ out_p,
                                          float* __restrict__ out_e){
    __shared__ float SA[64*68];
    __shared__ float SB[64*68];
    int t = threadIdx.x;
    int r0 = blockIdx.x * 64, d0 = blockIdx.y * 64;
    int mi4 = (t & 15) * 4, ni4 = (t >> 4) * 4;
    float dt = dt_of(dtp), hdt = 0.5f*dt;

    loadT64(SA, g_s2 + r0*HID, t);
    loadT64(SB, W1 + (size_t)d0*HID, t);
    __syncthreads();
    float acc[4][4] = {};
    mmaT<64>(acc, SA, SB, mi4, ni4);
    #pragma unroll
    for (int ii = 0; ii < 4; ++ii){
        int r = r0 + mi4 + ii;
        size_t off = (size_t)r*DIM + d0 + ni4;
        float4 ph = *(const float4*)(g_phalf + off);
        float4 pn;
        pn.x = ph.x - hdt*acc[ii][0];
        pn.y = ph.y - hdt*acc[ii][1];
        pn.z = ph.z - hdt*acc[ii][2];
        pn.w = ph.w - hdt*acc[ii][3];
        *(float4*)(out_p + off) = pn;
    }
    __syncthreads();

    loadT64(SA, g_h3 + r0*HID, t);
    loadT64(SB, g_W2T + (size_t)d0*HID, t);
    __syncthreads();
    float accH[4][4] = {};
    mmaT<64>(accH, SA, SB, mi4, ni4);
    float4 bv = *(const float4*)(b2 + d0 + ni4);
    #pragma unroll
    for (int ii = 0; ii < 4; ++ii){
        int r = r0 + mi4 + ii;
        size_t off = (size_t)r*DIM + d0 + ni4;
        float4 h1v = *(const float4*)(out_e + off);   // H1 stored by kB
        float4 ev;
        ev.x = fabsf(h1v.x - (accH[ii][0] + bv.x));
        ev.y = fabsf(h1v.y - (accH[ii][1] + bv.y));
        ev.z = fabsf(h1v.z - (accH[ii][2] + bv.z));
        ev.w = fabsf(h1v.w - (accH[ii][3] + bv.w));
        *(float4*)(out_e + off) = ev;
    }
}

// ---------------- launch ----------------
extern "C" void kernel_launch(void* const* d_in, const int* in_sizes, int n_in,
                              void* d_out, int out_size){
    const float* q    = (const float*)d_in[0];
    const float* p    = (const float*)d_in[1];
    const float* W1   = (const float*)d_in[2];
    const float* b1   = (const float*)d_in[3];
    const float* W2   = (const float*)d_in[4];
    const float* b2   = (const float*)d_in[5];
    const float* mass = (const float*)d_in[6];
    const float* dtp  = (const float*)d_in[7];
    float* out_q = (float*)d_out;
    float* out_p = out_q + (size_t)BB*DIM;
    float* out_e = out_p + (size_t)BB*DIM;

    prep_kernel<<<21, 256>>>(W1, W2, mass);
    kA<<<BB/64, 256>>>(q, p, W1, b1);
    dim3 g2(BB/64, DIM/64);
    kB<<<g2, 256>>>(q, p, W1, b2, dtp, out_q, out_e);
    kU<<<BB/64, 256>>>(W1, dtp);
    kD<<<g2, 256>>>(W1, b2, dtp, out_p, out_e);
}

// round 4
// speedup vs baseline: 1.4598x; 1.4598x over previous
#include <cuda_runtime.h>
#include <math.h>

#define BB   16384
#define DIM  1024
#define HID  64
#define TWOD 2048

typedef unsigned long long u64;

// small device scratch (allocations forbidden)
__device__ float g_w2s[HID];
__device__ float g_invm[DIM];
__device__ float g_Gq[HID*HID];   // W1q^T W1p
__device__ float g_Gm[HID*HID];   // W1q^T diag(1/m) W1q

// ---------------- helpers ----------------
__device__ __forceinline__ float dt_of(const float* dtp){
    float x = __ldg(dtp);
    return 1.0f/(1.0f + expf(-x));
}
__device__ __forceinline__ float gelu_f(float x){
    return x * 0.5f * (1.0f + erff(x * 0.70710678118654752440f));
}
__device__ __forceinline__ float dgelu_f(float x){
    float cdf = 0.5f * (1.0f + erff(x * 0.70710678118654752440f));
    float pdf = 0.39894228040143267794f * expf(-0.5f * x * x);
    return cdf + x * pdf;
}

// ---- packed f32x2 primitives ----
__device__ __forceinline__ u64 pk(float x, float y){
    u64 r; asm("mov.b64 %0, {%1,%2};" : "=l"(r) : "f"(x), "f"(y)); return r;
}
__device__ __forceinline__ u64 pk1(float x){
    u64 r; asm("mov.b64 %0, {%1,%1};" : "=l"(r) : "f"(x)); return r;
}
__device__ __forceinline__ void fma2(u64 &d, u64 a, u64 b){
    asm("fma.rn.f32x2 %0, %1, %2, %0;" : "+l"(d) : "l"(a), "l"(b));
}
__device__ __forceinline__ float2 up2(u64 v){
    float lo, hi; asm("mov.b64 {%0,%1}, %2;" : "=f"(lo), "=f"(hi) : "l"(v));
    return make_float2(lo, hi);
}

struct Acc { u64 v[4][2]; };
__device__ __forceinline__ void azero(Acc &A){
    #pragma unroll
    for (int i = 0; i < 4; ++i){ A.v[i][0] = 0ULL; A.v[i][1] = 0ULL; }
}
__device__ __forceinline__ void unpk(const Acc &A, float o[4][4]){
    #pragma unroll
    for (int i = 0; i < 4; ++i){
        float2 x0 = up2(A.v[i][0]), x1 = up2(A.v[i][1]);
        o[i][0] = x0.x; o[i][1] = x0.y; o[i][2] = x1.x; o[i][3] = x1.y;
    }
}

// one k-step: 4x4 MAC tile via 8 fma.f32x2
__device__ __forceinline__ void step1(Acc &A, float4 av, float4 bv){
    u64 b0 = pk(bv.x, bv.y), b1 = pk(bv.z, bv.w);
    u64 a0 = pk1(av.x), a1 = pk1(av.y), a2 = pk1(av.z), a3 = pk1(av.w);
    fma2(A.v[0][0], a0, b0); fma2(A.v[0][1], a0, b1);
    fma2(A.v[1][0], a1, b0); fma2(A.v[1][1], a1, b1);
    fma2(A.v[2][0], a2, b0); fma2(A.v[2][1], a2, b1);
    fma2(A.v[3][0], a3, b0); fma2(A.v[3][1], a3, b1);
}
// shared-a dual accumulation (z1 and v in one pass over p)
__device__ __forceinline__ void step2(Acc &Z, Acc &V, float4 av, float4 bz, float4 bq){
    u64 z0 = pk(bz.x, bz.y), z1 = pk(bz.z, bz.w);
    u64 q0 = pk(bq.x, bq.y), q1 = pk(bq.z, bq.w);
    u64 a0 = pk1(av.x), a1 = pk1(av.y), a2 = pk1(av.z), a3 = pk1(av.w);
    fma2(Z.v[0][0], a0, z0); fma2(Z.v[0][1], a0, z1);
    fma2(V.v[0][0], a0, q0); fma2(V.v[0][1], a0, q1);
    fma2(Z.v[1][0], a1, z0); fma2(Z.v[1][1], a1, z1);
    fma2(V.v[1][0], a1, q0); fma2(V.v[1][1], a1, q1);
    fma2(Z.v[2][0], a2, z0); fma2(Z.v[2][1], a2, z1);
    fma2(V.v[2][0], a2, q0); fma2(V.v[2][1], a2, q1);
    fma2(Z.v[3][0], a3, z0); fma2(Z.v[3][1], a3, z1);
    fma2(V.v[3][0], a3, q0); fma2(V.v[3][1], a3, q1);
}
// triple GEMM step: A1,A2 share b-operand bG; A3 uses bW
__device__ __forceinline__ void step3(Acc &A1, Acc &A2, Acc &A3,
                                      float4 a1, float4 a2, float4 a3,
                                      float4 bG, float4 bW){
    u64 g0 = pk(bG.x, bG.y), g1 = pk(bG.z, bG.w);
    u64 w0 = pk(bW.x, bW.y), w1 = pk(bW.z, bW.w);
    u64 x;
    x = pk1(a1.x); fma2(A1.v[0][0], x, g0); fma2(A1.v[0][1], x, g1);
    x = pk1(a1.y); fma2(A1.v[1][0], x, g0); fma2(A1.v[1][1], x, g1);
    x = pk1(a1.z); fma2(A1.v[2][0], x, g0); fma2(A1.v[2][1], x, g1);
    x = pk1(a1.w); fma2(A1.v[3][0], x, g0); fma2(A1.v[3][1], x, g1);
    x = pk1(a2.x); fma2(A2.v[0][0], x, g0); fma2(A2.v[0][1], x, g1);
    x = pk1(a2.y); fma2(A2.v[1][0], x, g0); fma2(A2.v[1][1], x, g1);
    x = pk1(a2.z); fma2(A2.v[2][0], x, g0); fma2(A2.v[2][1], x, g1);
    x = pk1(a2.w); fma2(A2.v[3][0], x, g0); fma2(A2.v[3][1], x, g1);
    x = pk1(a3.x); fma2(A3.v[0][0], x, w0); fma2(A3.v[0][1], x, w1);
    x = pk1(a3.y); fma2(A3.v[1][0], x, w0); fma2(A3.v[1][1], x, w1);
    x = pk1(a3.z); fma2(A3.v[2][0], x, w0); fma2(A3.v[2][1], x, w1);
    x = pk1(a3.w); fma2(A3.v[3][0], x, w0); fma2(A3.v[3][1], x, w1);
}

// ---------------- prep: w2s, invm, Gqp, Gm ----------------
__global__ __launch_bounds__(256) void prep_kernel(const float* __restrict__ W1,
                                                   const float* __restrict__ W2,
                                                   const float* __restrict__ mass){
    int b = blockIdx.x, t = threadIdx.x;
    if (b == 0){
        __shared__ float red[4][64];
        int row = t & 63, part = t >> 6;
        const float* src = W2 + (size_t)row*DIM + part*256;
        float s = 0.f;
        #pragma unroll 8
        for (int i = 0; i < 64; ++i){
            float4 v = *(const float4*)(src + i*4);
            s += v.x + v.y + v.z + v.w;
        }
        red[part][row] = s;
        for (int i = t; i < DIM; i += 256) g_invm[i] = 1.0f / mass[i];
        __syncthreads();
        if (part == 0) g_w2s[row] = red[0][row] + red[1][row] + red[2][row] + red[3][row];
    } else {
        // b 1..4 -> Gqp rows; b 5..8 -> Gm rows
        __shared__ float Xc[64][17];
        __shared__ float Yc[64][68];
        int variant = (b <= 4) ? 0 : 1;
        int i0 = ((b - 1) & 3) * 16;
        int i_ = t & 15, j4 = (t >> 4) * 4;
        float acc[4] = {0.f,0.f,0.f,0.f};
        for (int kc = 0; kc < DIM; kc += 64){
            for (int e = t; e < 1024; e += 256){
                int k = e >> 4, i = e & 15;
                Xc[k][i] = W1[(kc+k)*HID + i0 + i];
            }
            for (int e = t; e < 1024; e += 256){
                int k = e >> 4, c4 = e & 15;
                const float* src = W1 + (size_t)((variant ? 0 : DIM) + kc + k)*HID + c4*4;
                float4 v = *(const float4*)src;
                if (variant){
                    float s = 1.0f / mass[kc + k];
                    v.x *= s; v.y *= s; v.z *= s; v.w *= s;
                }
                *(float4*)&Yc[k][c4*4] = v;
            }
            __syncthreads();
            #pragma unroll 8
            for (int k = 0; k < 64; ++k){
                float x = Xc[k][i_];
                float4 y = *(const float4*)&Yc[k][j4];
                acc[0] = fmaf(x, y.x, acc[0]);
                acc[1] = fmaf(x, y.y, acc[1]);
                acc[2] = fmaf(x, y.z, acc[2]);
                acc[3] = fmaf(x, y.w, acc[3]);
            }
            __syncthreads();
        }
        float* dst = variant ? g_Gm : g_Gq;
        #pragma unroll
        for (int jj = 0; jj < 4; ++jj) dst[(i0+i_)*HID + j4+jj] = acc[jj];
    }
}

// ---------------- mega kernel: whole chain per 64-row block ----------------
// smem layout (floats):
//   R0  [0    :4352)  phase1 SA | SG (G1/Gqp/W1qT chunk)
//   R1  [4352 :8704)  phase1 SB + SBq | SW (W2 chunk)
//   S1T [8704 :13056) s1 transposed [j][r]
//   SCT [13056:17408) s2T then (s1+s2)T
//   SET [17408:21760) (h1-h3)T
#define SMEM_FLOATS 21760

__global__ __launch_bounds__(256, 2) void mega(const float* __restrict__ q,
                                               const float* __restrict__ p,
                                               const float* __restrict__ W1,
                                               const float* __restrict__ b1,
                                               const float* __restrict__ W2,
                                               const float* __restrict__ b2,
                                               const float* __restrict__ dtp,
                                               float* __restrict__ out_q,
                                               float* __restrict__ out_p,
                                               float* __restrict__ out_e){
    extern __shared__ float SM[];
    float* R0  = SM;
    float* R1  = SM + 4352;
    float* S1T = SM + 8704;
    float* SCT = SM + 13056;
    float* SET = SM + 17408;

    int t = threadIdx.x;
    int r0 = blockIdx.x * 64;
    int mi4 = (t & 15) * 4, ni4 = (t >> 4) * 4;
    float dt = dt_of(dtp), hdt = 0.5f*dt;

    Acc zA, vA; azero(zA); azero(vA);

    // ---- phase 1a: z1 += q @ W1q ----
    for (int kk = 0; kk < DIM; kk += 32){
        #pragma unroll
        for (int i2 = 0; i2 < 2; ++i2){
            int e = t + i2*256;
            int row = e >> 3, kq = e & 7;
            float4 v = *(const float4*)(q + (size_t)(r0+row)*DIM + kk + kq*4);
            R0[(kq*4+0)*68 + row] = v.x;
            R0[(kq*4+1)*68 + row] = v.y;
            R0[(kq*4+2)*68 + row] = v.z;
            R0[(kq*4+3)*68 + row] = v.w;
        }
        #pragma unroll
        for (int i2 = 0; i2 < 2; ++i2){
            int e = t + i2*256;
            int kr = e >> 4, c4 = e & 15;
            float4 v = *(const float4*)(W1 + (size_t)(kk+kr)*HID + c4*4);
            *(float4*)(R1 + kr*68 + c4*4) = v;
        }
        __syncthreads();
        #pragma unroll 8
        for (int k = 0; k < 32; ++k){
            float4 av = *(const float4*)(R0 + k*68 + mi4);
            float4 bv = *(const float4*)(R1 + k*68 + ni4);
            step1(zA, av, bv);
        }
        __syncthreads();
    }

    // ---- phase 1b: z1 += p @ W1p ; v += (p*invm) @ W1q ----
    float* RBq = R1 + 2176;
    for (int kk = 0; kk < DIM; kk += 32){
        #pragma unroll
        for (int i2 = 0; i2 < 2; ++i2){
            int e = t + i2*256;
            int row = e >> 3, kq = e & 7;
            float4 v = *(const float4*)(p + (size_t)(r0+row)*DIM + kk + kq*4);
            R0[(kq*4+0)*68 + row] = v.x;
            R0[(kq*4+1)*68 + row] = v.y;
            R0[(kq*4+2)*68 + row] = v.z;
            R0[(kq*4+3)*68 + row] = v.w;
        }
        #pragma unroll
        for (int i2 = 0; i2 < 2; ++i2){
            int e = t + i2*256;
            int kr = e >> 4, c4 = e & 15;
            float4 vz = *(const float4*)(W1 + (size_t)(DIM+kk+kr)*HID + c4*4);
            *(float4*)(R1 + kr*68 + c4*4) = vz;
            float4 vq = *(const float4*)(W1 + (size_t)(kk+kr)*HID + c4*4);
            float s = g_invm[kk + kr];
            vq.x *= s; vq.y *= s; vq.z *= s; vq.w *= s;
            *(float4*)(RBq + kr*68 + c4*4) = vq;
        }
        __syncthreads();
        #pragma unroll 8
        for (int k = 0; k < 32; ++k){
            float4 av = *(const float4*)(R0 + k*68 + mi4);
            float4 bz = *(const float4*)(R1 + k*68 + ni4);
            float4 bq = *(const float4*)(RBq + k*68 + ni4);
            step2(zA, vA, av, bz, bq);
        }
        __syncthreads();
    }

    // ---- phase 2: z1, h1, s1 ----
    float z1f[4][4], vf[4][4], hf1[4][4];
    unpk(zA, z1f); unpk(vA, vf);
    float4 b1v = *(const float4*)(b1 + ni4);
    float4 wsv = *(const float4*)(g_w2s + ni4);
    float bb[4] = {b1v.x, b1v.y, b1v.z, b1v.w};
    float ws[4] = {wsv.x, wsv.y, wsv.z, wsv.w};
    #pragma unroll
    for (int ii = 0; ii < 4; ++ii)
        #pragma unroll
        for (int jj = 0; jj < 4; ++jj){
            float z = z1f[ii][jj] + bb[jj];
            z1f[ii][jj] = z;
            hf1[ii][jj] = gelu_f(z);
            S1T[(ni4+jj)*68 + (mi4+ii)] = dgelu_f(z) * ws[jj];
        }
    // SG = G1 = hdt*Gqp + dt*hdt*Gm
    float dthdt = dt * hdt;
    for (int e = t; e < 1024; e += 256){
        int row = e >> 4, c4 = e & 15;
        int idx = row*64 + c4*4;
        float4 a = *(const float4*)(g_Gq + idx);
        float4 m4 = *(const float4*)(g_Gm + idx);
        float4 o;
        o.x = hdt*a.x + dthdt*m4.x;
        o.y = hdt*a.y + dthdt*m4.y;
        o.z = hdt*a.z + dthdt*m4.z;
        o.w = hdt*a.w + dthdt*m4.w;
        *(float4*)(R0 + row*68 + c4*4) = o;
    }
    __syncthreads();

    // ---- phase 3: z2 = z1 + dt*v - s1@G1 ----
    Acc cA; azero(cA);
    #pragma unroll 8
    for (int k = 0; k < 64; ++k){
        float4 av = *(const float4*)(S1T + k*68 + mi4);
        float4 bv = *(const float4*)(R0 + k*68 + ni4);
        step1(cA, av, bv);
    }
    float corr[4][4]; unpk(cA, corr);
    float z2f[4][4];
    #pragma unroll
    for (int ii = 0; ii < 4; ++ii)
        #pragma unroll
        for (int jj = 0; jj < 4; ++jj)
            z2f[ii][jj] = z1f[ii][jj] + dt*vf[ii][jj] - corr[ii][jj];
    __syncthreads();   // SG and SCT about to be (re)written

    // ---- phase 4: s2, z3 = z2 - hdt*(s2@Gqp), h3, E, C ----
    #pragma unroll
    for (int ii = 0; ii < 4; ++ii)
        #pragma unroll
        for (int jj = 0; jj < 4; ++jj)
            SCT[(ni4+jj)*68 + (mi4+ii)] = dgelu_f(z2f[ii][jj]) * ws[jj];
    for (int e = t; e < 1024; e += 256){
        int row = e >> 4, c4 = e & 15;
        float4 a = *(const float4*)(g_Gq + row*64 + c4*4);
        *(float4*)(R0 + row*68 + c4*4) = a;
    }
    __syncthreads();
    Acc c3A; azero(c3A);
    #pragma unroll 8
    for (int k = 0; k < 64; ++k){
        float4 av = *(const float4*)(SCT + k*68 + mi4);
        float4 bv = *(const float4*)(R0 + k*68 + ni4);
        step1(c3A, av, bv);
    }
    float c3[4][4]; unpk(c3A, c3);
    float ef[4][4];
    #pragma unroll
    for (int ii = 0; ii < 4; ++ii)
        #pragma unroll
        for (int jj = 0; jj < 4; ++jj){
            float z3 = z2f[ii][jj] - hdt*c3[ii][jj];
            ef[ii][jj] = hf1[ii][jj] - gelu_f(z3);
        }
    __syncthreads();   // SCT reads done; safe to overwrite
    #pragma unroll
    for (int ii = 0; ii < 4; ++ii)
        #pragma unroll
        for (int jj = 0; jj < 4; ++jj){
            int a = (ni4+jj)*68 + (mi4+ii);
            SET[a] = ef[ii][jj];
            SCT[a] = S1T[a] + SCT[a];   // C = s1 + s2
        }
    __syncthreads();

    // ---- phase 5: d-loop — Aq=s1@W1q^T, Cc=C@W1q^T, Ec=E@W2 ; outputs ----
    for (int dc = 0; dc < 16; ++dc){
        int d0 = dc * 64;
        #pragma unroll
        for (int i2 = 0; i2 < 4; ++i2){
            int e = t + i2*256;
            int row = e >> 4, c4 = e & 15;  // row = d', c4 -> j quad
            float4 v = *(const float4*)(W1 + (size_t)(d0+row)*HID + c4*4);
            R0[(c4*4+0)*68 + row] = v.x;
            R0[(c4*4+1)*68 + row] = v.y;
            R0[(c4*4+2)*68 + row] = v.z;
            R0[(c4*4+3)*68 + row] = v.w;
        }
        #pragma unroll
        for (int i2 = 0; i2 < 4; ++i2){
            int e = t + i2*256;
            int row = e >> 4, c4 = e & 15;  // row = j, c4 -> d' quad
            float4 v = *(const float4*)(W2 + (size_t)row*DIM + d0 + c4*4);
            *(float4*)(R1 + row*68 + c4*4) = v;
        }
        __syncthreads();
        Acc aA, cAq, eA; azero(aA); azero(cAq); azero(eA);
        #pragma unroll 8
        for (int k = 0; k < 64; ++k){
            float4 a1 = *(const float4*)(S1T + k*68 + mi4);
            float4 a2 = *(const float4*)(SCT + k*68 + mi4);
            float4 a3 = *(const float4*)(SET + k*68 + mi4);
            float4 bG = *(const float4*)(R0 + k*68 + ni4);
            float4 bW = *(const float4*)(R1 + k*68 + ni4);
            step3(aA, cAq, eA, a1, a2, a3, bG, bW);
        }
        float aq[4][4], cc[4][4], ec[4][4];
        unpk(aA, aq); unpk(cAq, cc); unpk(eA, ec);
        float4 iv = *(const float4*)(g_invm + d0 + ni4);
        float im[4] = {iv.x, iv.y, iv.z, iv.w};
        #pragma unroll
        for (int ii = 0; ii < 4; ++ii){
            size_t off = (size_t)(r0 + mi4 + ii)*DIM + d0 + ni4;
            float4 qv = *(const float4*)(q + off);
            float4 pv = *(const float4*)(p + off);
            float4 qn, pn, ev;
            float ph;
            ph = pv.x - hdt*aq[ii][0]; qn.x = qv.x + dt*im[0]*ph;
            ph = pv.y - hdt*aq[ii][1]; qn.y = qv.y + dt*im[1]*ph;
            ph = pv.z - hdt*aq[ii][2]; qn.z = qv.z + dt*im[2]*ph;
            ph = pv.w - hdt*aq[ii][3]; qn.w = qv.w + dt*im[3]*ph;
            pn.x = pv.x - hdt*cc[ii][0];
            pn.y = pv.y - hdt*cc[ii][1];
            pn.z = pv.z - hdt*cc[ii][2];
            pn.w = pv.w - hdt*cc[ii][3];
            ev.x = fabsf(ec[ii][0]);
            ev.y = fabsf(ec[ii][1]);
            ev.z = fabsf(ec[ii][2]);
            ev.w = fabsf(ec[ii][3]);
            *(float4*)(out_q + off) = qn;
            *(float4*)(out_p + off) = pn;
            *(float4*)(out_e + off) = ev;
        }
        __syncthreads();
    }
}

// ---------------- launch ----------------
extern "C" void kernel_launch(void* const* d_in, const int* in_sizes, int n_in,
                              void* d_out, int out_size){
    const float* q    = (const float*)d_in[0];
    const float* p    = (const float*)d_in[1];
    const float* W1   = (const float*)d_in[2];
    const float* b1   = (const float*)d_in[3];
    const float* W2   = (const float*)d_in[4];
    const float* b2   = (const float*)d_in[5];
    const float* mass = (const float*)d_in[6];
    const float* dtp  = (const float*)d_in[7];
    float* out_q = (float*)d_out;
    float* out_p = out_q + (size_t)BB*DIM;
    float* out_e = out_p + (size_t)BB*DIM;

    static int smem_set = 0;
    if (!smem_set){
        cudaFuncSetAttribute(mega, cudaFuncAttributeMaxDynamicSharedMemorySize,
                             SMEM_FLOATS * (int)sizeof(float));
        smem_set = 1;
    }
    prep_kernel<<<9, 256>>>(W1, W2, mass);
    mega<<<BB/64, 256, SMEM_FLOATS * sizeof(float)>>>(q, p, W1, b1, W2, b2, dtp,
                                                      out_q, out_p, out_e);
}

// round 5
// speedup vs baseline: 1.4649x; 1.0035x over previous
#include <cuda_runtime.h>
#include <math.h>

#define BB   16384
#define DIM  1024
#define HID  64
#define TWOD 2048

typedef unsigned long long u64;

// small device scratch (allocations forbidden)
__device__ float g_w2s[HID];
__device__ float g_invm[DIM];
__device__ float g_Gq[HID*HID];   // W1q^T W1p
__device__ float g_Gm[HID*HID];   // W1q^T diag(1/m) W1q

// ---------------- helpers ----------------
__device__ __forceinline__ float dt_of(const float* dtp){
    float x = __ldg(dtp);
    return 1.0f/(1.0f + expf(-x));
}
__device__ __forceinline__ float gelu_f(float x){
    return x * 0.5f * (1.0f + erff(x * 0.70710678118654752440f));
}
__device__ __forceinline__ float dgelu_f(float x){
    float cdf = 0.5f * (1.0f + erff(x * 0.70710678118654752440f));
    float pdf = 0.39894228040143267794f * expf(-0.5f * x * x);
    return cdf + x * pdf;
}

// ---- packed f32x2 primitives ----
__device__ __forceinline__ u64 pk(float x, float y){
    u64 r; asm("mov.b64 %0, {%1,%2};" : "=l"(r) : "f"(x), "f"(y)); return r;
}
__device__ __forceinline__ u64 pk1(float x){
    u64 r; asm("mov.b64 %0, {%1,%1};" : "=l"(r) : "f"(x)); return r;
}
__device__ __forceinline__ void fma2(u64 &d, u64 a, u64 b){
    asm("fma.rn.f32x2 %0, %1, %2, %0;" : "+l"(d) : "l"(a), "l"(b));
}
__device__ __forceinline__ float2 up2(u64 v){
    float lo, hi; asm("mov.b64 {%0,%1}, %2;" : "=f"(lo), "=f"(hi) : "l"(v));
    return make_float2(lo, hi);
}

struct Acc { u64 v[4][2]; };
__device__ __forceinline__ void azero(Acc &A){
    #pragma unroll
    for (int i = 0; i < 4; ++i){ A.v[i][0] = 0ULL; A.v[i][1] = 0ULL; }
}
__device__ __forceinline__ void unpk(const Acc &A, float o[4][4]){
    #pragma unroll
    for (int i = 0; i < 4; ++i){
        float2 x0 = up2(A.v[i][0]), x1 = up2(A.v[i][1]);
        o[i][0] = x0.x; o[i][1] = x0.y; o[i][2] = x1.x; o[i][3] = x1.y;
    }
}

// one k-step: 4x4 MAC tile via 8 fma.f32x2
__device__ __forceinline__ void step1(Acc &A, float4 av, float4 bv){
    u64 b0 = pk(bv.x, bv.y), b1 = pk(bv.z, bv.w);
    u64 a0 = pk1(av.x), a1 = pk1(av.y), a2 = pk1(av.z), a3 = pk1(av.w);
    fma2(A.v[0][0], a0, b0); fma2(A.v[0][1], a0, b1);
    fma2(A.v[1][0], a1, b0); fma2(A.v[1][1], a1, b1);
    fma2(A.v[2][0], a2, b0); fma2(A.v[2][1], a2, b1);
    fma2(A.v[3][0], a3, b0); fma2(A.v[3][1], a3, b1);
}
// shared-a dual accumulation (z1 and v in one pass over p)
__device__ __forceinline__ void step2(Acc &Z, Acc &V, float4 av, float4 bz, float4 bq){
    u64 z0 = pk(bz.x, bz.y), z1 = pk(bz.z, bz.w);
    u64 q0 = pk(bq.x, bq.y), q1 = pk(bq.z, bq.w);
    u64 a0 = pk1(av.x), a1 = pk1(av.y), a2 = pk1(av.z), a3 = pk1(av.w);
    fma2(Z.v[0][0], a0, z0); fma2(Z.v[0][1], a0, z1);
    fma2(V.v[0][0], a0, q0); fma2(V.v[0][1], a0, q1);
    fma2(Z.v[1][0], a1, z0); fma2(Z.v[1][1], a1, z1);
    fma2(V.v[1][0], a1, q0); fma2(V.v[1][1], a1, q1);
    fma2(Z.v[2][0], a2, z0); fma2(Z.v[2][1], a2, z1);
    fma2(V.v[2][0], a2, q0); fma2(V.v[2][1], a2, q1);
    fma2(Z.v[3][0], a3, z0); fma2(Z.v[3][1], a3, z1);
    fma2(V.v[3][0], a3, q0); fma2(V.v[3][1], a3, q1);
}
// triple GEMM step: A1,A2 share b-operand bG; A3 uses bW
__device__ __forceinline__ void step3(Acc &A1, Acc &A2, Acc &A3,
                                      float4 a1, float4 a2, float4 a3,
                                      float4 bG, float4 bW){
    u64 g0 = pk(bG.x, bG.y), g1 = pk(bG.z, bG.w);
    u64 w0 = pk(bW.x, bW.y), w1 = pk(bW.z, bW.w);
    u64 x;
    x = pk1(a1.x); fma2(A1.v[0][0], x, g0); fma2(A1.v[0][1], x, g1);
    x = pk1(a1.y); fma2(A1.v[1][0], x, g0); fma2(A1.v[1][1], x, g1);
    x = pk1(a1.z); fma2(A1.v[2][0], x, g0); fma2(A1.v[2][1], x, g1);
    x = pk1(a1.w); fma2(A1.v[3][0], x, g0); fma2(A1.v[3][1], x, g1);
    x = pk1(a2.x); fma2(A2.v[0][0], x, g0); fma2(A2.v[0][1], x, g1);
    x = pk1(a2.y); fma2(A2.v[1][0], x, g0); fma2(A2.v[1][1], x, g1);
    x = pk1(a2.z); fma2(A2.v[2][0], x, g0); fma2(A2.v[2][1], x, g1);
    x = pk1(a2.w); fma2(A2.v[3][0], x, g0); fma2(A2.v[3][1], x, g1);
    x = pk1(a3.x); fma2(A3.v[0][0], x, w0); fma2(A3.v[0][1], x, w1);
    x = pk1(a3.y); fma2(A3.v[1][0], x, w0); fma2(A3.v[1][1], x, w1);
    x = pk1(a3.z); fma2(A3.v[2][0], x, w0); fma2(A3.v[2][1], x, w1);
    x = pk1(a3.w); fma2(A3.v[3][0], x, w0); fma2(A3.v[3][1], x, w1);
}

// ---------------- prep: w2s, invm, Gqp, Gm ----------------
__global__ __launch_bounds__(256) void prep_kernel(const float* __restrict__ W1,
                                                   const float* __restrict__ W2,
                                                   const float* __restrict__ mass){
    int b = blockIdx.x, t = threadIdx.x;
    if (b == 0){
        __shared__ float red[4][64];
        int row = t & 63, part = t >> 6;
        const float* src = W2 + (size_t)row*DIM + part*256;
        float s = 0.f;
        #pragma unroll 8
        for (int i = 0; i < 64; ++i){
            float4 v = *(const float4*)(src + i*4);
            s += v.x + v.y + v.z + v.w;
        }
        red[part][row] = s;
        for (int i = t; i < DIM; i += 256) g_invm[i] = 1.0f / mass[i];
        __syncthreads();
        if (part == 0) g_w2s[row] = red[0][row] + red[1][row] + red[2][row] + red[3][row];
    } else {
        // b 1..4 -> Gqp rows; b 5..8 -> Gm rows
        __shared__ float Xc[64][17];
        __shared__ float Yc[64][68];
        int variant = (b <= 4) ? 0 : 1;
        int i0 = ((b - 1) & 3) * 16;
        int i_ = t & 15, j4 = (t >> 4) * 4;
        float acc[4] = {0.f,0.f,0.f,0.f};
        for (int kc = 0; kc < DIM; kc += 64){
            for (int e = t; e < 1024; e += 256){
                int k = e >> 4, i = e & 15;
                Xc[k][i] = W1[(kc+k)*HID + i0 + i];
            }
            for (int e = t; e < 1024; e += 256){
                int k = e >> 4, c4 = e & 15;
                const float* src = W1 + (size_t)((variant ? 0 : DIM) + kc + k)*HID + c4*4;
                float4 v = *(const float4*)src;
                if (variant){
                    float s = 1.0f / mass[kc + k];
                    v.x *= s; v.y *= s; v.z *= s; v.w *= s;
                }
                *(float4*)&Yc[k][c4*4] = v;
            }
            __syncthreads();
            #pragma unroll 8
            for (int k = 0; k < 64; ++k){
                float x = Xc[k][i_];
                float4 y = *(const float4*)&Yc[k][j4];
                acc[0] = fmaf(x, y.x, acc[0]);
                acc[1] = fmaf(x, y.y, acc[1]);
                acc[2] = fmaf(x, y.z, acc[2]);
                acc[3] = fmaf(x, y.w, acc[3]);
            }
            __syncthreads();
        }
        float* dst = variant ? g_Gm : g_Gq;
        #pragma unroll
        for (int jj = 0; jj < 4; ++jj) dst[(i0+i_)*HID + j4+jj] = acc[jj];
    }
}

// ---------------- mega kernel: whole chain per 64-row block ----------------
// smem layout (floats):
//   R0  [0    :4352)  phase1 SA | SG (G1/Gqp/W1qT chunk)
//   R1  [4352 :8704)  phase1 SB + SBq | SW (W2 chunk)
//   S1T [8704 :13056) s1 transposed [j][r]
//   SCT [13056:17408) s2T then (s1+s2)T
//   SET [17408:21760) (h1-h3)T
#define SMEM_FLOATS 21760

__global__ __launch_bounds__(256, 2) void mega(const float* __restrict__ q,
                                               const float* __restrict__ p,
                                               const float* __restrict__ W1,
                                               const float* __restrict__ b1,
                                               const float* __restrict__ W2,
                                               const float* __restrict__ b2,
                                               const float* __restrict__ dtp,
                                               float* __restrict__ out_q,
                                               float* __restrict__ out_p,
                                               float* __restrict__ out_e){
    extern __shared__ float SM[];
    float* R0  = SM;
    float* R1  = SM + 4352;
    float* S1T = SM + 8704;
    float* SCT = SM + 13056;
    float* SET = SM + 17408;

    int t = threadIdx.x;
    int r0 = blockIdx.x * 64;
    int mi4 = (t & 15) * 4, ni4 = (t >> 4) * 4;
    float dt = dt_of(dtp), hdt = 0.5f*dt;

    Acc zA, vA; azero(zA); azero(vA);

    // ---- phase 1a: z1 += q @ W1q ----
    for (int kk = 0; kk < DIM; kk += 32){
        #pragma unroll
        for (int i2 = 0; i2 < 2; ++i2){
            int e = t + i2*256;
            int row = e >> 3, kq = e & 7;
            float4 v = *(const float4*)(q + (size_t)(r0+row)*DIM + kk + kq*4);
            R0[(kq*4+0)*68 + row] = v.x;
            R0[(kq*4+1)*68 + row] = v.y;
            R0[(kq*4+2)*68 + row] = v.z;
            R0[(kq*4+3)*68 + row] = v.w;
        }
        #pragma unroll
        for (int i2 = 0; i2 < 2; ++i2){
            int e = t + i2*256;
            int kr = e >> 4, c4 = e & 15;
            float4 v = *(const float4*)(W1 + (size_t)(kk+kr)*HID + c4*4);
            *(float4*)(R1 + kr*68 + c4*4) = v;
        }
        __syncthreads();
        #pragma unroll 8
        for (int k = 0; k < 32; ++k){
            float4 av = *(const float4*)(R0 + k*68 + mi4);
            float4 bv = *(const float4*)(R1 + k*68 + ni4);
            step1(zA, av, bv);
        }
        __syncthreads();
    }

    // ---- phase 1b: z1 += p @ W1p ; v += (p*invm) @ W1q ----
    float* RBq = R1 + 2176;
    for (int kk = 0; kk < DIM; kk += 32){
        #pragma unroll
        for (int i2 = 0; i2 < 2; ++i2){
            int e = t + i2*256;
            int row = e >> 3, kq = e & 7;
            float4 v = *(const float4*)(p + (size_t)(r0+row)*DIM + kk + kq*4);
            R0[(kq*4+0)*68 + row] = v.x;
            R0[(kq*4+1)*68 + row] = v.y;
            R0[(kq*4+2)*68 + row] = v.z;
            R0[(kq*4+3)*68 + row] = v.w;
        }
        #pragma unroll
        for (int i2 = 0; i2 < 2; ++i2){
            int e = t + i2*256;
            int kr = e >> 4, c4 = e & 15;
            float4 vz = *(const float4*)(W1 + (size_t)(DIM+kk+kr)*HID + c4*4);
            *(float4*)(R1 + kr*68 + c4*4) = vz;
            float4 vq = *(const float4*)(W1 + (size_t)(kk+kr)*HID + c4*4);
            float s = g_invm[kk + kr];
            vq.x *= s; vq.y *= s; vq.z *= s; vq.w *= s;
            *(float4*)(RBq + kr*68 + c4*4) = vq;
        }
        __syncthreads();
        #pragma unroll 8
        for (int k = 0; k < 32; ++k){
            float4 av = *(const float4*)(R0 + k*68 + mi4);
            float4 bz = *(const float4*)(R1 + k*68 + ni4);
            float4 bq = *(const float4*)(RBq + k*68 + ni4);
            step2(zA, vA, av, bz, bq);
        }
        __syncthreads();
    }

    // ---- phase 2: z1, h1, s1 ----
    float z1f[4][4], vf[4][4], hf1[4][4];
    unpk(zA, z1f); unpk(vA, vf);
    float4 b1v = *(const float4*)(b1 + ni4);
    float4 wsv = *(const float4*)(g_w2s + ni4);
    float bb[4] = {b1v.x, b1v.y, b1v.z, b1v.w};
    float ws[4] = {wsv.x, wsv.y, wsv.z, wsv.w};
    #pragma unroll
    for (int ii = 0; ii < 4; ++ii)
        #pragma unroll
        for (int jj = 0; jj < 4; ++jj){
            float z = z1f[ii][jj] + bb[jj];
            z1f[ii][jj] = z;
            hf1[ii][jj] = gelu_f(z);
            S1T[(ni4+jj)*68 + (mi4+ii)] = dgelu_f(z) * ws[jj];
        }
    // SG = G1 = hdt*Gqp + dt*hdt*Gm
    float dthdt = dt * hdt;
    for (int e = t; e < 1024; e += 256){
        int row = e >> 4, c4 = e & 15;
        int idx = row*64 + c4*4;
        float4 a = *(const float4*)(g_Gq + idx);
        float4 m4 = *(const float4*)(g_Gm + idx);
        float4 o;
        o.x = hdt*a.x + dthdt*m4.x;
        o.y = hdt*a.y + dthdt*m4.y;
        o.z = hdt*a.z + dthdt*m4.z;
        o.w = hdt*a.w + dthdt*m4.w;
        *(float4*)(R0 + row*68 + c4*4) = o;
    }
    __syncthreads();

    // ---- phase 3: z2 = z1 + dt*v - s1@G1 ----
    Acc cA; azero(cA);
    #pragma unroll 8
    for (int k = 0; k < 64; ++k){
        float4 av = *(const float4*)(S1T + k*68 + mi4);
        float4 bv = *(const float4*)(R0 + k*68 + ni4);
        step1(cA, av, bv);
    }
    float corr[4][4]; unpk(cA, corr);
    float z2f[4][4];
    #pragma unroll
    for (int ii = 0; ii < 4; ++ii)
        #pragma unroll
        for (int jj = 0; jj < 4; ++jj)
            z2f[ii][jj] = z1f[ii][jj] + dt*vf[ii][jj] - corr[ii][jj];
    __syncthreads();   // SG and SCT about to be (re)written

    // ---- phase 4: s2, z3 = z2 - hdt*(s2@Gqp), h3, E, C ----
    #pragma unroll
    for (int ii = 0; ii < 4; ++ii)
        #pragma unroll
        for (int jj = 0; jj < 4; ++jj)
            SCT[(ni4+jj)*68 + (mi4+ii)] = dgelu_f(z2f[ii][jj]) * ws[jj];
    for (int e = t; e < 1024; e += 256){
        int row = e >> 4, c4 = e & 15;
        float4 a = *(const float4*)(g_Gq + row*64 + c4*4);
        *(float4*)(R0 + row*68 + c4*4) = a;
    }
    __syncthreads();
    Acc c3A; azero(c3A);
    #pragma unroll 8
    for (int k = 0; k < 64; ++k){
        float4 av = *(const float4*)(SCT + k*68 + mi4);
        float4 bv = *(const float4*)(R0 + k*68 + ni4);
        step1(c3A, av, bv);
    }
    float c3[4][4]; unpk(c3A, c3);
    float ef[4][4];
    #pragma unroll
    for (int ii = 0; ii < 4; ++ii)
        #pragma unroll
        for (int jj = 0; jj < 4; ++jj){
            float z3 = z2f[ii][jj] - hdt*c3[ii][jj];
            ef[ii][jj] = hf1[ii][jj] - gelu_f(z3);
        }
    __syncthreads();   // SCT reads done; safe to overwrite
    #pragma unroll
    for (int ii = 0; ii < 4; ++ii)
        #pragma unroll
        for (int jj = 0; jj < 4; ++jj){
            int a = (ni4+jj)*68 + (mi4+ii);
            SET[a] = ef[ii][jj];
            SCT[a] = S1T[a] + SCT[a];   // C = s1 + s2
        }
    __syncthreads();

    // ---- phase 5: d-loop — Aq=s1@W1q^T, Cc=C@W1q^T, Ec=E@W2 ; outputs ----
    for (int dc = 0; dc < 16; ++dc){
        int d0 = dc * 64;
        #pragma unroll
        for (int i2 = 0; i2 < 4; ++i2){
            int e = t + i2*256;
            int row = e >> 4, c4 = e & 15;  // row = d', c4 -> j quad
            float4 v = *(const float4*)(W1 + (size_t)(d0+row)*HID + c4*4);
            R0[(c4*4+0)*68 + row] = v.x;
            R0[(c4*4+1)*68 + row] = v.y;
            R0[(c4*4+2)*68 + row] = v.z;
            R0[(c4*4+3)*68 + row] = v.w;
        }
        #pragma unroll
        for (int i2 = 0; i2 < 4; ++i2){
            int e = t + i2*256;
            int row = e >> 4, c4 = e & 15;  // row = j, c4 -> d' quad
            float4 v = *(const float4*)(W2 + (size_t)row*DIM + d0 + c4*4);
            *(float4*)(R1 + row*68 + c4*4) = v;
        }
        __syncthreads();
        Acc aA, cAq, eA; azero(aA); azero(cAq); azero(eA);
        #pragma unroll 8
        for (int k = 0; k < 64; ++k){
            float4 a1 = *(const float4*)(S1T + k*68 + mi4);
            float4 a2 = *(const float4*)(SCT + k*68 + mi4);
            float4 a3 = *(const float4*)(SET + k*68 + mi4);
            float4 bG = *(const float4*)(R0 + k*68 + ni4);
            float4 bW = *(const float4*)(R1 + k*68 + ni4);
            step3(aA, cAq, eA, a1, a2, a3, bG, bW);
        }
        float aq[4][4], cc[4][4], ec[4][4];
        unpk(aA, aq); unpk(cAq, cc); unpk(eA, ec);
        float4 iv = *(const float4*)(g_invm + d0 + ni4);
        float im[4] = {iv.x, iv.y, iv.z, iv.w};
        #pragma unroll
        for (int ii = 0; ii < 4; ++ii){
            size_t off = (size_t)(r0 + mi4 + ii)*DIM + d0 + ni4;
            float4 qv = *(const float4*)(q + off);
            float4 pv = *(const float4*)(p + off);
            float4 qn, pn, ev;
            float ph;
            ph = pv.x - hdt*aq[ii][0]; qn.x = qv.x + dt*im[0]*ph;
            ph = pv.y - hdt*aq[ii][1]; qn.y = qv.y + dt*im[1]*ph;
            ph = pv.z - hdt*aq[ii][2]; qn.z = qv.z + dt*im[2]*ph;
            ph = pv.w - hdt*aq[ii][3]; qn.w = qv.w + dt*im[3]*ph;
            pn.x = pv.x - hdt*cc[ii][0];
            pn.y = pv.y - hdt*cc[ii][1];
            pn.z = pv.z - hdt*cc[ii][2];
            pn.w = pv.w - hdt*cc[ii][3];
            ev.x = fabsf(ec[ii][0]);
            ev.y = fabsf(ec[ii][1]);
            ev.z = fabsf(ec[ii][2]);
            ev.w = fabsf(ec[ii][3]);
            *(float4*)(out_q + off) = qn;
            *(float4*)(out_p + off) = pn;
            *(float4*)(out_e + off) = ev;
        }
        __syncthreads();
    }
}

// ---------------- launch ----------------
extern "C" void kernel_launch(void* const* d_in, const int* in_sizes, int n_in,
                              void* d_out, int out_size){
    const float* q    = (const float*)d_in[0];
    const float* p    = (const float*)d_in[1];
    const float* W1   = (const float*)d_in[2];
    const float* b1   = (const float*)d_in[3];
    const float* W2   = (const float*)d_in[4];
    const float* b2   = (const float*)d_in[5];
    const float* mass = (const float*)d_in[6];
    const float* dtp  = (const float*)d_in[7];
    float* out_q = (float*)d_out;
    float* out_p = out_q + (size_t)BB*DIM;
    float* out_e = out_p + (size_t)BB*DIM;

    static int smem_set = 0;
    if (!smem_set){
        cudaFuncSetAttribute(mega, cudaFuncAttributeMaxDynamicSharedMemorySize,
                             SMEM_FLOATS * (int)sizeof(float));
        smem_set = 1;
    }
    prep_kernel<<<9, 256>>>(W1, W2, mass);
    mega<<<BB/64, 256, SMEM_FLOATS * sizeof(float)>>>(q, p, W1, b1, W2, b2, dtp,
                                                      out_q, out_p, out_e);
}

// round 8
// speedup vs baseline: 2.6316x; 1.7965x over previous
#include <cuda_runtime.h>
#include <cuda_bf16.h>
#include <math.h>
#include <stdint.h>

#define BB   16384
#define DIM  1024
#define HID  64

typedef uint32_t u32;

// ---------------- device scratch (no allocations allowed) ----------------
__device__ float g_w2s[HID];
__device__ float g_invm[DIM];
__device__ float g_Gq[HID*HID];   // W1q^T W1p
__device__ float g_Gm[HID*HID];   // W1q^T diag(1/m) W1q

// bf16 hi/lo pre-split weights
__device__ __align__(16) __nv_bfloat16 g_W1qT_h[HID*DIM],  g_W1qT_l[HID*DIM];   // [j][k]
__device__ __align__(16) __nv_bfloat16 g_W1pT_h[HID*DIM],  g_W1pT_l[HID*DIM];   // [j][k]
__device__ __align__(16) __nv_bfloat16 g_W1qmT_h[HID*DIM], g_W1qmT_l[HID*DIM];  // [j][k] invm folded
__device__ __align__(16) __nv_bfloat16 g_W1qB_h[DIM*HID],  g_W1qB_l[DIM*HID];   // [d][j]
__device__ __align__(16) __nv_bfloat16 g_W2TB_h[DIM*HID],  g_W2TB_l[DIM*HID];   // [d][j] = W2[j][d]
__device__ __align__(16) __nv_bfloat16 g_G1T_h[HID*HID],   g_G1T_l[HID*HID];    // [j2][j1] hdt*Gq+dt*hdt*Gm
__device__ __align__(16) __nv_bfloat16 g_GqT_h[HID*HID],   g_GqT_l[HID*HID];    // [j2][j1] hdt*Gq

// ---------------- scalar helpers ----------------
__device__ __forceinline__ float dt_of(const float* dtp){
    float x = __ldg(dtp);
    return 1.0f/(1.0f + expf(-x));
}
__device__ __forceinline__ float gelu_f(float x){
    return x * 0.5f * (1.0f + erff(x * 0.70710678118654752440f));
}
__device__ __forceinline__ float dgelu_f(float x){
    float cdf = 0.5f * (1.0f + erff(x * 0.70710678118654752440f));
    float pdf = 0.39894228040143267794f * expf(-0.5f * x * x);
    return cdf + x * pdf;
}

// ---------------- smem primitives ----------------
__device__ __forceinline__ u32 s2u(const void* p){
    u32 a;
    asm("{ .reg .u64 t; cvta.to.shared.u64 t, %1; cvt.u32.u64 %0, t; }" : "=r"(a) : "l"(p));
    return a;
}
__device__ __forceinline__ void sts16(u32 a, unsigned short v){ asm volatile("st.shared.b16 [%0], %1;" :: "r"(a), "h"(v)); }
__device__ __forceinline__ void sts32f(u32 a, float v){ asm volatile("st.shared.f32 [%0], %1;" :: "r"(a), "f"(v)); }
__device__ __forceinline__ void sts64(u32 a, u32 x, u32 y){ asm volatile("st.shared.v2.b32 [%0], {%1,%2};" :: "r"(a), "r"(x), "r"(y)); }
__device__ __forceinline__ void sts128(u32 a, uint4 v){ asm volatile("st.shared.v4.b32 [%0], {%1,%2,%3,%4};" :: "r"(a), "r"(v.x), "r"(v.y), "r"(v.z), "r"(v.w)); }
__device__ __forceinline__ float ldsf(u32 a){ float v; asm volatile("ld.shared.f32 %0, [%1];" : "=f"(v) : "r"(a)); return v; }

__device__ __forceinline__ u32 pack2(__nv_bfloat16 a, __nv_bfloat16 b){
    return (u32)__bfloat16_as_ushort(a) | ((u32)__bfloat16_as_ushort(b) << 16);
}

// ---------------- MMA primitives ----------------
// A-tile fragment (m16 x k16) from [row][k] layout, row stride 144 bytes
__device__ __forceinline__ void ldA(u32 base, int rowbase, int ks, int l, u32 a[4]){
    u32 addr = base + (u32)(rowbase + (l & 15))*144u + (u32)(((l >> 4)*8 + ks*16)*2);
    asm volatile("ldmatrix.sync.aligned.m8n8.x4.shared.b16 {%0,%1,%2,%3}, [%4];"
        : "=r"(a[0]), "=r"(a[1]), "=r"(a[2]), "=r"(a[3]) : "r"(addr));
}
// B-tile fragment (n8 x k16) from [n][k] layout, row stride 144 bytes
__device__ __forceinline__ void ldB(u32 base, int nrow, int ks, int l, u32 b[2]){
    u32 addr = base + (u32)(nrow + (l & 7))*144u + (u32)(((((l >> 3) & 1)*8) + ks*16)*2);
    asm volatile("ldmatrix.sync.aligned.m8n8.x2.shared.b16 {%0,%1}, [%2];"
        : "=r"(b[0]), "=r"(b[1]) : "r"(addr));
}
__device__ __forceinline__ void mm(float c[4], const u32 a[4], const u32 b[2]){
    asm volatile("mma.sync.aligned.m16n8k16.row.col.f32.bf16.bf16.f32 "
        "{%0,%1,%2,%3}, {%4,%5,%6,%7}, {%8,%9}, {%0,%1,%2,%3};"
        : "+f"(c[0]), "+f"(c[1]), "+f"(c[2]), "+f"(c[3])
        : "r"(a[0]), "r"(a[1]), "r"(a[2]), "r"(a[3]), "r"(b[0]), "r"(b[1]));
}

// K=64 3-term GEMM: acc[2][4][4] += A(128x64 hi/lo) x B(64x64 hi/lo)^T
__device__ __forceinline__ void gemmK64(float acc[2][4][4], u32 AH, u32 AL,
                                        u32 BH, u32 BL, int mr, int nc, int l){
    #pragma unroll
    for (int ks = 0; ks < 4; ++ks){
        u32 ah[2][4], al[2][4];
        ldA(AH, mr,     ks, l, ah[0]);
        ldA(AH, mr+16,  ks, l, ah[1]);
        ldA(AL, mr,     ks, l, al[0]);
        ldA(AL, mr+16,  ks, l, al[1]);
        #pragma unroll
        for (int nb = 0; nb < 4; ++nb){
            u32 bh[2], bl[2];
            ldB(BH, nc + nb*8, ks, l, bh);
            ldB(BL, nc + nb*8, ks, l, bl);
            #pragma unroll
            for (int i = 0; i < 2; ++i){
                mm(acc[i][nb], ah[i], bh);
                mm(acc[i][nb], ah[i], bl);
                mm(acc[i][nb], al[i], bh);
            }
        }
    }
}
// dual-B variant: accZ += A x B0, accV += A x B1 (shared A fragments)
__device__ __forceinline__ void gemmK64_dualB(float accZ[2][4][4], float accV[2][4][4],
                                              u32 AH, u32 AL,
                                              u32 B0H, u32 B0L, u32 B1H, u32 B1L,
                                              int mr, int nc, int l){
    #pragma unroll
    for (int ks = 0; ks < 4; ++ks){
        u32 ah[2][4], al[2][4];
        ldA(AH, mr,     ks, l, ah[0]);
        ldA(AH, mr+16,  ks, l, ah[1]);
        ldA(AL, mr,     ks, l, al[0]);
        ldA(AL, mr+16,  ks, l, al[1]);
        #pragma unroll
        for (int nb = 0; nb < 4; ++nb){
            u32 bh[2], bl[2], ch[2], cl[2];
            ldB(B0H, nc + nb*8, ks, l, bh);
            ldB(B0L, nc + nb*8, ks, l, bl);
            ldB(B1H, nc + nb*8, ks, l, ch);
            ldB(B1L, nc + nb*8, ks, l, cl);
            #pragma unroll
            for (int i = 0; i < 2; ++i){
                mm(accZ[i][nb], ah[i], bh);
                mm(accZ[i][nb], ah[i], bl);
                mm(accZ[i][nb], al[i], bh);
                mm(accV[i][nb], ah[i], ch);
                mm(accV[i][nb], ah[i], cl);
                mm(accV[i][nb], al[i], ch);
            }
        }
    }
}

// convert 128x64 fp32 chunk (row stride DIM) -> hi/lo bf16 tiles [128][72]
__device__ __forceinline__ void conv_tile(u32 dh, u32 dl, const float* __restrict__ src, int t){
    #pragma unroll
    for (int i = 0; i < 8; ++i){
        int e = t + i*256;
        int row = e >> 4, c4 = e & 15;
        float4 v = *(const float4*)(src + (size_t)row*DIM + c4*4);
        __nv_bfloat16 h0=__float2bfloat16_rn(v.x), h1=__float2bfloat16_rn(v.y),
                      h2=__float2bfloat16_rn(v.z), h3=__float2bfloat16_rn(v.w);
        float l0=v.x-__bfloat162float(h0), l1=v.y-__bfloat162float(h1),
              l2=v.z-__bfloat162float(h2), l3=v.w-__bfloat162float(h3);
        u32 off = (u32)(row*144 + c4*8);
        sts64(dh + off, pack2(h0,h1), pack2(h2,h3));
        sts64(dl + off, pack2(__float2bfloat16_rn(l0),__float2bfloat16_rn(l1)),
                        pack2(__float2bfloat16_rn(l2),__float2bfloat16_rn(l3)));
    }
}
// copy 64x64 bf16 tile (row stride 'stride' elems) -> [64][72]
__device__ __forceinline__ void copy_bt(u32 dst, const __nv_bfloat16* __restrict__ src, int stride, int t){
    #pragma unroll
    for (int i = 0; i < 2; ++i){
        int e = t + i*256;
        int row = e >> 3, k8 = e & 7;
        uint4 v = *(const uint4*)(src + (size_t)row*stride + k8*8);
        sts128(dst + (u32)(row*144 + k8*16), v);
    }
}
// store one fp32 value split hi/lo into bf16 tiles at (row, col)
__device__ __forceinline__ void put_split(u32 th, u32 tl, int row, int col, float x){
    u32 off = (u32)(row*144 + col*2);
    __nv_bfloat16 h = __float2bfloat16_rn(x);
    float lo = x - __bfloat162float(h);
    sts16(th + off, __bfloat16_as_ushort(h));
    sts16(tl + off, __bfloat16_as_ushort(__float2bfloat16_rn(lo)));
}

// ---------------- prep1: w2s, invm, Gq, Gm ----------------
__global__ __launch_bounds__(256) void prep_kernel(const float* __restrict__ W1,
                                                   const float* __restrict__ W2,
                                                   const float* __restrict__ mass){
    int b = blockIdx.x, t = threadIdx.x;
    if (b == 0){
        __shared__ float red[4][64];
        int row = t & 63, part = t >> 6;
        const float* src = W2 + (size_t)row*DIM + part*256;
        float s = 0.f;
        #pragma unroll 8
        for (int i = 0; i < 64; ++i){
            float4 v = *(const float4*)(src + i*4);
            s += v.x + v.y + v.z + v.w;
        }
        red[part][row] = s;
        for (int i = t; i < DIM; i += 256) g_invm[i] = 1.0f / mass[i];
        __syncthreads();
        if (part == 0) g_w2s[row] = red[0][row] + red[1][row] + red[2][row] + red[3][row];
    } else {
        __shared__ float Xc[64][17];
        __shared__ float Yc[64][68];
        int variant = (b <= 4) ? 0 : 1;
        int i0 = ((b - 1) & 3) * 16;
        int i_ = t & 15, j4 = (t >> 4) * 4;
        float acc[4] = {0.f,0.f,0.f,0.f};
        for (int kc = 0; kc < DIM; kc += 64){
            for (int e = t; e < 1024; e += 256){
                int k = e >> 4, i = e & 15;
                Xc[k][i] = W1[(kc+k)*HID + i0 + i];
            }
            for (int e = t; e < 1024; e += 256){
                int k = e >> 4, c4 = e & 15;
                const float* src = W1 + (size_t)((variant ? 0 : DIM) + kc + k)*HID + c4*4;
                float4 v = *(const float4*)src;
                if (variant){
                    float s = 1.0f / mass[kc + k];
                    v.x *= s; v.y *= s; v.z *= s; v.w *= s;
                }
                *(float4*)&Yc[k][c4*4] = v;
            }
            __syncthreads();
            #pragma unroll 8
            for (int k = 0; k < 64; ++k){
                float x = Xc[k][i_];
                float4 y = *(const float4*)&Yc[k][j4];
                acc[0] = fmaf(x, y.x, acc[0]);
                acc[1] = fmaf(x, y.y, acc[1]);
                acc[2] = fmaf(x, y.z, acc[2]);
                acc[3] = fmaf(x, y.w, acc[3]);
            }
            __syncthreads();
        }
        float* dst = variant ? g_Gm : g_Gq;
        #pragma unroll
        for (int jj = 0; jj < 4; ++jj) dst[(i0+i_)*HID + j4+jj] = acc[jj];
    }
}

// ---------------- prep2: bf16 hi/lo splits ----------------
__device__ __forceinline__ void split_st(__nv_bfloat16* H, __nv_bfloat16* L, int i, float x){
    __nv_bfloat16 h = __float2bfloat16_rn(x);
    H[i] = h;
    L[i] = __float2bfloat16_rn(x - __bfloat162float(h));
}
__global__ __launch_bounds__(256) void prep2_kernel(const float* __restrict__ W1,
                                                    const float* __restrict__ W2,
                                                    const float* __restrict__ dtp){
    float dt = dt_of(dtp), hdt = 0.5f*dt;
    int g = blockIdx.x*256 + threadIdx.x;
    int S = gridDim.x*256;
    for (int idx = g; idx < HID*DIM; idx += S){
        int j = idx >> 10, k = idx & 1023;
        float x = W1[k*HID + j];
        split_st(g_W1qT_h,  g_W1qT_l,  idx, x);
        split_st(g_W1pT_h,  g_W1pT_l,  idx, W1[(DIM + k)*HID + j]);
        split_st(g_W1qmT_h, g_W1qmT_l, idx, x * g_invm[k]);
    }
    for (int idx = g; idx < DIM*HID; idx += S){
        int d = idx >> 6, j = idx & 63;
        split_st(g_W1qB_h, g_W1qB_l, idx, W1[d*HID + j]);
        split_st(g_W2TB_h, g_W2TB_l, idx, W2[(size_t)j*DIM + d]);
    }
    for (int idx = g; idx < HID*HID; idx += S){
        int j2 = idx >> 6, j1 = idx & 63;
        float gq = g_Gq[j1*HID + j2];
        float gm = g_Gm[j1*HID + j2];
        split_st(g_G1T_h, g_G1T_l, idx, hdt*gq + dt*hdt*gm);
        split_st(g_GqT_h, g_GqT_l, idx, hdt*gq);
    }
}

// ---------------- smem layout (bytes) ----------------
#define XH_   0u
#define XL_   18432u
#define B0H_  36864u
#define B0L_  46080u
#define B1H_  55296u
#define B1L_  64512u
#define S1H_  73728u
#define S1L_  92160u
#define CTH_  110592u
#define CTL_  129024u
#define ETH_  147456u
#define ETL_  165888u
#define CB1_  184320u
#define CWS_  184576u
#define SMEM_TOTAL 184832

// ---------------- mega kernel ----------------
__global__ __launch_bounds__(256, 1) void mega(const float* __restrict__ q,
                                               const float* __restrict__ p,
                                               const float* __restrict__ b1,
                                               const float* __restrict__ dtp,
                                               float* __restrict__ out_q,
                                               float* __restrict__ out_p,
                                               float* __restrict__ out_e){
    extern __shared__ char smem[];
    u32 SB = s2u(smem);
    int t = threadIdx.x, w = t >> 5, l = t & 31;
    int mr = (w & 3) * 32;         // warp row base within 128
    int nc = (w >> 2) * 32;        // warp col base within 64
    int r0 = blockIdx.x * 128;
    float dt = dt_of(dtp), hdt = 0.5f*dt;

    if (t < 64){
        sts32f(SB + CB1_ + t*4, __ldg(b1 + t));
        sts32f(SB + CWS_ + t*4, g_w2s[t]);
    }

    // ================= phase 1: Z and V accumulation over K =================
    // K = 1024 per side -> 16 chunks of 64 for q, 16 for p.  (R7 bug: was 32+32.)
    float accZ[2][4][4], accV[2][4][4];
    #pragma unroll
    for (int i = 0; i < 2; ++i)
        #pragma unroll
        for (int nb = 0; nb < 4; ++nb)
            #pragma unroll
            for (int c = 0; c < 4; ++c){ accZ[i][nb][c] = 0.f; accV[i][nb][c] = 0.f; }

    for (int ch = 0; ch < 32; ++ch){
        int is_p = (ch >= 16);
        int kk = (ch & 15) * 64;
        __syncthreads();
        conv_tile(SB+XH_, SB+XL_, (is_p ? p : q) + (size_t)r0*DIM + kk, t);
        if (!is_p){
            copy_bt(SB+B0H_, g_W1qT_h + kk, DIM, t);
            copy_bt(SB+B0L_, g_W1qT_l + kk, DIM, t);
        } else {
            copy_bt(SB+B0H_, g_W1pT_h + kk, DIM, t);
            copy_bt(SB+B0L_, g_W1pT_l + kk, DIM, t);
            copy_bt(SB+B1H_, g_W1qmT_h + kk, DIM, t);
            copy_bt(SB+B1L_, g_W1qmT_l + kk, DIM, t);
        }
        __syncthreads();
        if (!is_p){
            gemmK64(accZ, SB+XH_, SB+XL_, SB+B0H_, SB+B0L_, mr, nc, l);
        } else {
            gemmK64_dualB(accZ, accV, SB+XH_, SB+XL_,
                          SB+B0H_, SB+B0L_, SB+B1H_, SB+B1L_, mr, nc, l);
        }
    }
    __syncthreads();

    // ================= phase 2: z1, s1 =================
    float z1r[2][4][4], z2r[2][4][4];
    #pragma unroll
    for (int i = 0; i < 2; ++i)
        #pragma unroll
        for (int nb = 0; nb < 4; ++nb){
            int colb = nc + nb*8 + 2*(l & 3);
            #pragma unroll
            for (int c = 0; c < 4; ++c){
                int col = colb + (c & 1);
                int row = mr + i*16 + (l >> 2) + 8*(c >> 1);
                float z1 = accZ[i][nb][c] + ldsf(SB + CB1_ + col*4);
                float ws = ldsf(SB + CWS_ + col*4);
                z1r[i][nb][c] = z1;
                z2r[i][nb][c] = fmaf(dt, accV[i][nb][c], z1);   // z1 + dt*v (corr pending)
                put_split(SB+S1H_, SB+S1L_, row, col, dgelu_f(z1)*ws);
            }
        }
    // Gram tiles: B0 = G1T (hdt*Gq + dt*hdt*Gm), B1 = GqT (hdt*Gq)
    copy_bt(SB+B0H_, g_G1T_h, 64, t);
    copy_bt(SB+B0L_, g_G1T_l, 64, t);
    copy_bt(SB+B1H_, g_GqT_h, 64, t);
    copy_bt(SB+B1L_, g_GqT_l, 64, t);
    __syncthreads();

    // ================= phase 3: corr = s1@G1 ; z2, s2 =================
    {
        float cr[2][4][4] = {};
        gemmK64(cr, SB+S1H_, SB+S1L_, SB+B0H_, SB+B0L_, mr, nc, l);
        #pragma unroll
        for (int i = 0; i < 2; ++i)
            #pragma unroll
            for (int nb = 0; nb < 4; ++nb){
                int colb = nc + nb*8 + 2*(l & 3);
                #pragma unroll
                for (int c = 0; c < 4; ++c){
                    int col = colb + (c & 1);
                    int row = mr + i*16 + (l >> 2) + 8*(c >> 1);
                    float z2 = z2r[i][nb][c] - cr[i][nb][c];
                    z2r[i][nb][c] = z2;
                    float ws = ldsf(SB + CWS_ + col*4);
                    put_split(SB+CTH_, SB+CTL_, row, col, dgelu_f(z2)*ws);   // s2
                }
            }
    }
    __syncthreads();

    // ================= phase 4: c3 = s2@(hdt*Gq) ; E, C =================
    {
        float c3[2][4][4] = {};
        gemmK64(c3, SB+CTH_, SB+CTL_, SB+B1H_, SB+B1L_, mr, nc, l);
        __syncthreads();   // everyone done reading CT before overwrite
        #pragma unroll
        for (int i = 0; i < 2; ++i)
            #pragma unroll
            for (int nb = 0; nb < 4; ++nb){
                int colb = nc + nb*8 + 2*(l & 3);
                #pragma unroll
                for (int c = 0; c < 4; ++c){
                    int col = colb + (c & 1);
                    int row = mr + i*16 + (l >> 2) + 8*(c >> 1);
                    float z1 = z1r[i][nb][c];
                    float z2 = z2r[i][nb][c];
                    float z3 = z2 - c3[i][nb][c];
                    float ws = ldsf(SB + CWS_ + col*4);
                    put_split(SB+ETH_, SB+ETL_, row, col, gelu_f(z1) - gelu_f(z3));       // E
                    put_split(SB+CTH_, SB+CTL_, row, col, (dgelu_f(z1) + dgelu_f(z2))*ws); // C
                }
            }
    }

    // ================= phase 5: d-loop =================
    for (int dc = 0; dc < 16; ++dc){
        int d0 = dc * 64;
        __syncthreads();
        copy_bt(SB+B0H_, g_W1qB_h + (size_t)d0*HID, HID, t);
        copy_bt(SB+B0L_, g_W1qB_l + (size_t)d0*HID, HID, t);
        copy_bt(SB+B1H_, g_W2TB_h + (size_t)d0*HID, HID, t);
        copy_bt(SB+B1L_, g_W2TB_l + (size_t)d0*HID, HID, t);
        __syncthreads();

        float aq[2][4][4] = {}, cc[2][4][4] = {};
        gemmK64(aq, SB+S1H_, SB+S1L_, SB+B0H_, SB+B0L_, mr, nc, l);
        gemmK64(cc, SB+CTH_, SB+CTL_, SB+B0H_, SB+B0L_, mr, nc, l);
        #pragma unroll
        for (int i = 0; i < 2; ++i)
            #pragma unroll
            for (int nb = 0; nb < 4; ++nb){
                int col = nc + nb*8 + 2*(l & 3);
                #pragma unroll
                for (int h = 0; h < 2; ++h){
                    int row = mr + i*16 + (l >> 2) + 8*h;
                    size_t off = (size_t)(r0 + row)*DIM + d0 + col;
                    float2 qv = *(const float2*)(q + off);
                    float2 pv = *(const float2*)(p + off);
                    float2 iv = *(const float2*)(g_invm + d0 + col);
                    float a0 = aq[i][nb][2*h], a1 = aq[i][nb][2*h+1];
                    float c0 = cc[i][nb][2*h], c1 = cc[i][nb][2*h+1];
                    float2 qn, pn;
                    qn.x = qv.x + dt*iv.x*(pv.x - hdt*a0);
                    qn.y = qv.y + dt*iv.y*(pv.y - hdt*a1);
                    pn.x = pv.x - hdt*c0;
                    pn.y = pv.y - hdt*c1;
                    *(float2*)(out_q + off) = qn;
                    *(float2*)(out_p + off) = pn;
                }
            }

        float ec[2][4][4] = {};
        gemmK64(ec, SB+ETH_, SB+ETL_, SB+B1H_, SB+B1L_, mr, nc, l);
        #pragma unroll
        for (int i = 0; i < 2; ++i)
            #pragma unroll
            for (int nb = 0; nb < 4; ++nb){
                int col = nc + nb*8 + 2*(l & 3);
                #pragma unroll
                for (int h = 0; h < 2; ++h){
                    int row = mr + i*16 + (l >> 2) + 8*h;
                    size_t off = (size_t)(r0 + row)*DIM + d0 + col;
                    float2 ev;
                    ev.x = fabsf(ec[i][nb][2*h]);
                    ev.y = fabsf(ec[i][nb][2*h+1]);
                    *(float2*)(out_e + off) = ev;
                }
            }
    }
}

// ---------------- launch ----------------
extern "C" void kernel_launch(void* const* d_in, const int* in_sizes, int n_in,
                              void* d_out, int out_size){
    const float* q    = (const float*)d_in[0];
    const float* p    = (const float*)d_in[1];
    const float* W1   = (const float*)d_in[2];
    const float* b1   = (const float*)d_in[3];
    const float* W2   = (const float*)d_in[4];
    const float* mass = (const float*)d_in[6];
    const float* dtp  = (const float*)d_in[7];
    float* out_q = (float*)d_out;
    float* out_p = out_q + (size_t)BB*DIM;
    float* out_e = out_p + (size_t)BB*DIM;

    cudaFuncSetAttribute(mega, cudaFuncAttributeMaxDynamicSharedMemorySize, SMEM_TOTAL);

    prep_kernel<<<9, 256>>>(W1, W2, mass);
    prep2_kernel<<<64, 256>>>(W1, W2, dtp);
    mega<<<BB/128, 256, SMEM_TOTAL>>>(q, p, b1, dtp, out_q, out_p, out_e);
}